// round 2
// baseline (speedup 1.0000x reference)
#include <cuda_runtime.h>
#include <cuda_bf16.h>

// Problem: BoundaryLoss — mean(sigmoid(logits) * EDT2D(target))
// Shapes: logits f32 [8,1,256,256], target i32 [8,1,256,256], out f32 scalar.
//
// Stage 1: per-row exact 1D distance (prefix-max / suffix-min scans), squared,
//          into device-global scratch (2 MB).
// Stage 2: per-pixel exact 2D squared EDT via expanding-radius search:
//          D2(i,w) = min_j dr2[j,w] + (i-j)^2. Since j=i is included,
//          cur <= dr2[i,w], and once r^2 >= cur no farther j can win.
//          Fused sigmoid + scaled reduction into d_out.

#define B 8
#define H 256
#define W 256
#define NPIX (B * H * W)          // 524288
#define BIGD 1000000.0f

__device__ float g_dr2[NPIX];     // scratch: squared 1D row distances

__global__ void k_rowdist(const int* __restrict__ target,
                          float* __restrict__ out)
{
    if (blockIdx.x == 0 && threadIdx.x == 0) *out = 0.0f;

    const int row = blockIdx.x;          // b*H + i
    const int w   = threadIdx.x;         // 0..255
    const int base = row * W;

    const int fg = target[base + w] > 0;

    __shared__ int s[W];

    // ---- nearest fg index to the LEFT (inclusive): prefix max of (fg? w : -1)
    s[w] = fg ? w : -1;
    __syncthreads();
#pragma unroll
    for (int off = 1; off < W; off <<= 1) {
        int v = (w >= off) ? s[w - off] : -1;
        __syncthreads();
        if (v > s[w]) s[w] = v;
        __syncthreads();
    }
    const int lastL = s[w];
    __syncthreads();

    // ---- nearest fg index to the RIGHT (inclusive): suffix min of (fg? w : 2W)
    s[w] = fg ? w : (2 * W);
    __syncthreads();
#pragma unroll
    for (int off = 1; off < W; off <<= 1) {
        int v = (w + off < W) ? s[w + off] : (2 * W);
        __syncthreads();
        if (v < s[w]) s[w] = v;
        __syncthreads();
    }
    const int nextR = s[w];

    const float dl = (lastL >= 0) ? (float)(w - lastL) : BIGD;
    const float dr = (nextR < W) ? (float)(nextR - w) : BIGD;
    const float d  = fminf(dl, dr);
    g_dr2[base + w] = d * d;
}

__global__ void k_edt_loss(const float* __restrict__ logits,
                           float* __restrict__ out)
{
    const int idx = blockIdx.x * blockDim.x + threadIdx.x;   // 0..NPIX-1
    const int i   = (idx >> 8) & (H - 1);                    // row within image

    float cur = g_dr2[idx];

    // Expanding-radius exact column min: min_j dr2[j,w] + (i-j)^2.
    // Warp-uniform loop; lanes already converged skip the loads.
    int r = 1;
    while (r < H && __any_sync(0xffffffffu, (float)(r * r) < cur)) {
        const float rr = (float)(r * r);
        if (rr < cur) {
            if (i - r >= 0) cur = fminf(cur, g_dr2[idx - (r << 8)] + rr);
            if (i + r < H)  cur = fminf(cur, g_dr2[idx + (r << 8)] + rr);
        }
        ++r;
    }

    const float x    = logits[idx];
    const float prob = 1.0f / (1.0f + __expf(-x));
    float val = prob * sqrtf(cur) * (1.0f / (float)NPIX);

    // warp reduction
#pragma unroll
    for (int o = 16; o; o >>= 1)
        val += __shfl_xor_sync(0xffffffffu, val, o);

    __shared__ float ws[8];
    if ((threadIdx.x & 31) == 0) ws[threadIdx.x >> 5] = val;
    __syncthreads();

    if (threadIdx.x == 0) {
        float v = ws[0];
#pragma unroll
        for (int k = 1; k < 8; ++k) v += ws[k];
        atomicAdd(out, v);
    }
}

extern "C" void kernel_launch(void* const* d_in, const int* in_sizes, int n_in,
                              void* d_out, int out_size)
{
    const float* logits = (const float*)d_in[0];
    const int*   target = (const int*)d_in[1];
    float*       out    = (float*)d_out;

    k_rowdist<<<B * H, W>>>(target, out);
    k_edt_loss<<<NPIX / 256, 256>>>(logits, out);
}